// round 4
// baseline (speedup 1.0000x reference)
#include <cuda_runtime.h>
#include <cstdint>

// Problem constants: B=1, Z=1, X=Y=360, C=80, Np=1,993,728
#define XDIM  360
#define YDIM  360
#define CDIM  80
#define CELLS (XDIM * YDIM)          // 129600 = 4050 * 32
#define NP_MAX 2000000
#define SCAN_NB 127                  // ceil(129600/1024)

__device__ __align__(256) int g_cell[NP_MAX];      // cell per point, -1 dropped
__device__ __align__(256) int g_count[CELLS];      // histogram
__device__ __align__(256) int g_offset[CELLS];     // exclusive scan
__device__ __align__(256) int g_cursor[CELLS];     // reorder cursors
__device__ __align__(256) int g_pid[NP_MAX];       // point ids sorted by cell
__device__ int g_blocksum[SCAN_NB];

// ---------------------------------------------------------------------------
// 1) zero histogram counters
// ---------------------------------------------------------------------------
__global__ void zero_counts_kernel() {
    int i = blockIdx.x * blockDim.x + threadIdx.x;
    if (i < CELLS) g_count[i] = 0;
}

// ---------------------------------------------------------------------------
// 2) cell index + histogram.
// XLA rewrites (v-lo)/DX into (v-lo)*(1/DX) with rn-rounded f32 reciprocal —
// replicate exactly (validated: rel_err ~4e-8).
// ---------------------------------------------------------------------------
__global__ void idx_hist_kernel(const float* __restrict__ geom, int np) {
    int p = blockIdx.x * blockDim.x + threadIdx.x;
    if (p >= np) return;

    float gx = geom[3 * (size_t)p + 0];
    float gy = geom[3 * (size_t)p + 1];
    float gz = geom[3 * (size_t)p + 2];

    const float lox = -53.85f - 0.3f * 0.5f;   // -54.0f in f32
    const float loz =   0.0f  - 20.0f * 0.5f;  // -10.0f
    const float rxy = 1.0f / 0.3f;             // rn f32 reciprocal
    const float rz  = 1.0f / 20.0f;            // exact

    int xi = (int)floorf((gx - lox) * rxy);
    int yi = (int)floorf((gy - lox) * rxy);
    int zi = (int)floorf((gz - loz) * rz);

    bool kept = (xi >= 0) & (xi < XDIM) & (yi >= 0) & (yi < YDIM) &
                (zi >= 0) & (zi < 1);
    int cell = kept ? (xi * YDIM + yi) : -1;
    g_cell[p] = cell;
    if (cell >= 0) atomicAdd(&g_count[cell], 1);
}

// ---------------------------------------------------------------------------
// 3a) per-block exclusive scan of counts (1024 elems/block)
// ---------------------------------------------------------------------------
__global__ __launch_bounds__(1024) void scan_block_kernel() {
    __shared__ int warpsum[32];
    int t = threadIdx.x;
    int gid = blockIdx.x * 1024 + t;
    int v = (gid < CELLS) ? g_count[gid] : 0;

    int x = v;
    #pragma unroll
    for (int d = 1; d < 32; d <<= 1) {
        int y = __shfl_up_sync(0xFFFFFFFFu, x, d);
        if ((t & 31) >= d) x += y;
    }
    if ((t & 31) == 31) warpsum[t >> 5] = x;
    __syncthreads();
    if (t < 32) {
        int w = warpsum[t];
        #pragma unroll
        for (int d = 1; d < 32; d <<= 1) {
            int y = __shfl_up_sync(0xFFFFFFFFu, w, d);
            if (t >= d) w += y;
        }
        warpsum[t] = w;
    }
    __syncthreads();
    int base = (t >= 32) ? warpsum[(t >> 5) - 1] : 0;
    int incl = x + base;
    if (gid < CELLS) g_offset[gid] = incl - v;       // exclusive
    if (t == 1023) g_blocksum[blockIdx.x] = incl;    // block total
}

// ---------------------------------------------------------------------------
// 3b) add block bases, materialize offsets + cursors
// ---------------------------------------------------------------------------
__global__ __launch_bounds__(1024) void scan_add_kernel() {
    __shared__ int bs[SCAN_NB];
    int t = threadIdx.x, b = blockIdx.x;
    if (t < SCAN_NB) bs[t] = g_blocksum[t];
    __syncthreads();
    int base = 0;
    for (int j = 0; j < b; j++) base += bs[j];
    int gid = b * 1024 + t;
    if (gid < CELLS) {
        int o = g_offset[gid] + base;
        g_offset[gid] = o;
        g_cursor[gid] = o;
    }
}

// ---------------------------------------------------------------------------
// 4) reorder: bucket point ids by cell
// ---------------------------------------------------------------------------
__global__ void reorder_kernel(int np) {
    int p = blockIdx.x * blockDim.x + threadIdx.x;
    if (p >= np) return;
    int cell = g_cell[p];
    if (cell < 0) return;
    int pos = atomicAdd(&g_cursor[cell], 1);
    g_pid[pos] = p;
}

// ---------------------------------------------------------------------------
// 5) gather: warp per cell; lanes 0..19 own one float4 of C=80.
//    NEW: pids for the cell are prefetched cooperatively (one per lane,
//    coalesced) and broadcast via shfl -> all ~15 feats loads per cell are
//    independent (MLP ~15 instead of ~2). __ldcs on feats (pure streaming).
//    Block = 32 warps = 32 consecutive xy cells; epilogue transposes through
//    smem and writes out[c][xy] 128B-coalesced. No float atomics.
// ---------------------------------------------------------------------------
__global__ __launch_bounds__(1024) void gather_kernel(
    const float* __restrict__ feats, float* __restrict__ out)
{
    __shared__ float s[32][81];   // [local cell][channel], stride 81: no conflicts

    int lane = threadIdx.x & 31;
    int wid  = threadIdx.x >> 5;            // local cell 0..31
    int cell = blockIdx.x * 32 + wid;       // CELLS = 4050*32 exact

    int start = g_offset[cell];
    int cnt   = g_count[cell];

    const float4* f4 = reinterpret_cast<const float4*>(feats);
    const bool active = (lane < 20);
    float4 acc = make_float4(0.f, 0.f, 0.f, 0.f);

    for (int base = 0; base < cnt; base += 32) {
        int n = cnt - base;
        if (n > 32) n = 32;
        // cooperative pid prefetch: one coalesced LDG per lane
        int pid_l = (lane < n) ? g_pid[start + base + lane] : 0;

        #pragma unroll 4
        for (int k = 0; k < n; k++) {
            int p = __shfl_sync(0xFFFFFFFFu, pid_l, k);
            if (active) {
                float4 v = __ldcs(&f4[(size_t)p * 20 + lane]);
                acc.x += v.x; acc.y += v.y; acc.z += v.z; acc.w += v.w;
            }
        }
    }

    if (active) {
        int c = 4 * lane;
        s[wid][c + 0] = acc.x;
        s[wid][c + 1] = acc.y;
        s[wid][c + 2] = acc.z;
        s[wid][c + 3] = acc.w;
    }
    __syncthreads();

    // write out: 80 c x 32 xy = 2560 floats; each warp covers 32 consecutive xy
    int xy0 = blockIdx.x * 32;
    #pragma unroll
    for (int r = 0; r < 3; r++) {
        int linear = r * 1024 + threadIdx.x;
        if (linear < CDIM * 32) {
            int c = linear >> 5;          // channel
            int x = linear & 31;          // local xy
            out[(size_t)c * CELLS + xy0 + x] = s[x][c];
        }
    }
}

// ---------------------------------------------------------------------------
// Launch
// ---------------------------------------------------------------------------
extern "C" void kernel_launch(void* const* d_in, const int* in_sizes, int n_in,
                              void* d_out, int out_size)
{
    const float* geom  = (const float*)d_in[0];
    const float* feats = (const float*)d_in[1];
    float* out = (float*)d_out;

    int np = in_sizes[0] / 3;   // 1,993,728

    zero_counts_kernel<<<(CELLS + 255) / 256, 256>>>();
    idx_hist_kernel<<<(np + 255) / 256, 256>>>(geom, np);
    scan_block_kernel<<<SCAN_NB, 1024>>>();
    scan_add_kernel<<<SCAN_NB, 1024>>>();
    reorder_kernel<<<(np + 255) / 256, 256>>>(np);
    gather_kernel<<<CELLS / 32, 1024>>>(feats, out);
}

// round 5
// speedup vs baseline: 1.0767x; 1.0767x over previous
#include <cuda_runtime.h>
#include <cstdint>

// Problem constants: B=1, Z=1, X=Y=360, C=80, Np=1,993,728
#define XDIM  360
#define YDIM  360
#define CDIM  80
#define CELLS (XDIM * YDIM)          // 129600 = 4050 * 32
#define NP_MAX 2000000
#define SCAN_NB 127                  // ceil(129600/1024)

__device__ __align__(256) int g_cell[NP_MAX];      // cell per point, -1 dropped
__device__ __align__(256) int g_count[CELLS];      // histogram
__device__ __align__(256) int g_offset[CELLS];     // exclusive scan
__device__ __align__(256) int g_cursor[CELLS];     // reorder cursors
__device__ __align__(256) int g_pid[NP_MAX];       // point ids sorted by cell
__device__ int g_blocksum[SCAN_NB];
__device__ int g_blockbase[SCAN_NB];

// ---------------------------------------------------------------------------
// 1) zero histogram counters
// ---------------------------------------------------------------------------
__global__ void zero_counts_kernel() {
    int i = blockIdx.x * blockDim.x + threadIdx.x;
    if (i < CELLS) g_count[i] = 0;
}

// ---------------------------------------------------------------------------
// 2) cell index + histogram.
// XLA rewrites (v-lo)/DX into (v-lo)*(1/DX) with rn-rounded f32 reciprocal —
// replicate exactly (validated: rel_err ~4e-8).
// ---------------------------------------------------------------------------
__global__ void idx_hist_kernel(const float* __restrict__ geom, int np) {
    int p = blockIdx.x * blockDim.x + threadIdx.x;
    if (p >= np) return;

    float gx = geom[3 * (size_t)p + 0];
    float gy = geom[3 * (size_t)p + 1];
    float gz = geom[3 * (size_t)p + 2];

    const float lox = -53.85f - 0.3f * 0.5f;   // -54.0f in f32
    const float loz =   0.0f  - 20.0f * 0.5f;  // -10.0f
    const float rxy = 1.0f / 0.3f;             // rn f32 reciprocal
    const float rz  = 1.0f / 20.0f;            // exact

    int xi = (int)floorf((gx - lox) * rxy);
    int yi = (int)floorf((gy - lox) * rxy);
    int zi = (int)floorf((gz - loz) * rz);

    bool kept = (xi >= 0) & (xi < XDIM) & (yi >= 0) & (yi < YDIM) &
                (zi >= 0) & (zi < 1);
    int cell = kept ? (xi * YDIM + yi) : -1;
    g_cell[p] = cell;
    if (cell >= 0) atomicAdd(&g_count[cell], 1);
}

// ---------------------------------------------------------------------------
// 3a) per-block exclusive scan of counts (1024 elems/block)
// ---------------------------------------------------------------------------
__global__ __launch_bounds__(1024) void scan_block_kernel() {
    __shared__ int warpsum[32];
    int t = threadIdx.x;
    int gid = blockIdx.x * 1024 + t;
    int v = (gid < CELLS) ? g_count[gid] : 0;

    int x = v;
    #pragma unroll
    for (int d = 1; d < 32; d <<= 1) {
        int y = __shfl_up_sync(0xFFFFFFFFu, x, d);
        if ((t & 31) >= d) x += y;
    }
    if ((t & 31) == 31) warpsum[t >> 5] = x;
    __syncthreads();
    if (t < 32) {
        int w = warpsum[t];
        #pragma unroll
        for (int d = 1; d < 32; d <<= 1) {
            int y = __shfl_up_sync(0xFFFFFFFFu, w, d);
            if (t >= d) w += y;
        }
        warpsum[t] = w;
    }
    __syncthreads();
    int base = (t >= 32) ? warpsum[(t >> 5) - 1] : 0;
    int incl = x + base;
    if (gid < CELLS) g_offset[gid] = incl - v;       // exclusive
    if (t == 1023) g_blocksum[blockIdx.x] = incl;    // block total
}

// ---------------------------------------------------------------------------
// 3b) spine scan: exclusive scan of the 127 block sums (single block)
// ---------------------------------------------------------------------------
__global__ __launch_bounds__(128) void scan_spine_kernel() {
    __shared__ int warpsum[4];
    int t = threadIdx.x;
    int v = (t < SCAN_NB) ? g_blocksum[t] : 0;

    int x = v;
    #pragma unroll
    for (int d = 1; d < 32; d <<= 1) {
        int y = __shfl_up_sync(0xFFFFFFFFu, x, d);
        if ((t & 31) >= d) x += y;
    }
    if ((t & 31) == 31) warpsum[t >> 5] = x;
    __syncthreads();
    if (t < 4) {
        int w = warpsum[t];
        #pragma unroll
        for (int d = 1; d < 4; d <<= 1) {
            int y = __shfl_up_sync(0xFu, w, d);
            if (t >= d) w += y;
        }
        warpsum[t] = w;
    }
    __syncthreads();
    int base = (t >= 32) ? warpsum[(t >> 5) - 1] : 0;
    if (t < SCAN_NB) g_blockbase[t] = x + base - v;  // exclusive
}

// ---------------------------------------------------------------------------
// 3c) add block bases, materialize offsets + cursors
// ---------------------------------------------------------------------------
__global__ __launch_bounds__(1024) void scan_add_kernel() {
    int b = blockIdx.x;
    int base = g_blockbase[b];           // uniform load, broadcast
    int gid = b * 1024 + threadIdx.x;
    if (gid < CELLS) {
        int o = g_offset[gid] + base;
        g_offset[gid] = o;
        g_cursor[gid] = o;
    }
}

// ---------------------------------------------------------------------------
// 4) reorder: bucket point ids by cell
// ---------------------------------------------------------------------------
__global__ void reorder_kernel(int np) {
    int p = blockIdx.x * blockDim.x + threadIdx.x;
    if (p >= np) return;
    int cell = g_cell[p];
    if (cell < 0) return;
    int pos = atomicAdd(&g_cursor[cell], 1);
    g_pid[pos] = p;
}

// ---------------------------------------------------------------------------
// 5) gather: warp per cell; lanes 0..19 own one float4 of C=80.
//    Pids staged through smem: one coalesced LDG per 32-chunk, then the inner
//    loop is LDS(29cyc) + independent LDG.128, unrolled x4 -> MLP~4/warp with
//    no shfl in the chain. Block = 32 warps = 32 consecutive xy cells;
//    epilogue transposes via smem, out writes 128B-coalesced. No float atomics.
// ---------------------------------------------------------------------------
__global__ __launch_bounds__(1024) void gather_kernel(
    const float* __restrict__ feats, float* __restrict__ out)
{
    __shared__ float s[32][81];        // [local cell][channel]
    __shared__ int   spid[32][32];     // per-warp pid staging

    int lane = threadIdx.x & 31;
    int wid  = threadIdx.x >> 5;            // local cell 0..31
    int cell = blockIdx.x * 32 + wid;       // CELLS = 4050*32 exact

    int start = g_offset[cell];
    int cnt   = g_count[cell];

    const float4* f4 = reinterpret_cast<const float4*>(feats);
    const bool active = (lane < 20);
    float4 acc = make_float4(0.f, 0.f, 0.f, 0.f);

    for (int base = 0; base < cnt; base += 32) {
        int n = cnt - base;
        if (n > 32) n = 32;
        // coalesced pid prefetch into smem (one 128B LDG per chunk)
        if (lane < n) spid[wid][lane] = g_pid[start + base + lane];
        __syncwarp();

        if (active) {
            int k = 0;
            #pragma unroll 4
            for (; k + 4 <= n; k += 4) {
                int p0 = spid[wid][k + 0];
                int p1 = spid[wid][k + 1];
                int p2 = spid[wid][k + 2];
                int p3 = spid[wid][k + 3];
                float4 v0 = f4[(size_t)p0 * 20 + lane];
                float4 v1 = f4[(size_t)p1 * 20 + lane];
                float4 v2 = f4[(size_t)p2 * 20 + lane];
                float4 v3 = f4[(size_t)p3 * 20 + lane];
                acc.x += v0.x; acc.y += v0.y; acc.z += v0.z; acc.w += v0.w;
                acc.x += v1.x; acc.y += v1.y; acc.z += v1.z; acc.w += v1.w;
                acc.x += v2.x; acc.y += v2.y; acc.z += v2.z; acc.w += v2.w;
                acc.x += v3.x; acc.y += v3.y; acc.z += v3.z; acc.w += v3.w;
            }
            for (; k < n; k++) {
                int p0 = spid[wid][k];
                float4 v0 = f4[(size_t)p0 * 20 + lane];
                acc.x += v0.x; acc.y += v0.y; acc.z += v0.z; acc.w += v0.w;
            }
        }
        __syncwarp();
    }

    if (active) {
        int c = 4 * lane;
        s[wid][c + 0] = acc.x;
        s[wid][c + 1] = acc.y;
        s[wid][c + 2] = acc.z;
        s[wid][c + 3] = acc.w;
    }
    __syncthreads();

    // write out: 80 c x 32 xy; each warp covers 32 consecutive xy
    int xy0 = blockIdx.x * 32;
    #pragma unroll
    for (int r = 0; r < 3; r++) {
        int linear = r * 1024 + threadIdx.x;
        if (linear < CDIM * 32) {
            int c = linear >> 5;          // channel
            int x = linear & 31;          // local xy
            out[(size_t)c * CELLS + xy0 + x] = s[x][c];
        }
    }
}

// ---------------------------------------------------------------------------
// Launch
// ---------------------------------------------------------------------------
extern "C" void kernel_launch(void* const* d_in, const int* in_sizes, int n_in,
                              void* d_out, int out_size)
{
    const float* geom  = (const float*)d_in[0];
    const float* feats = (const float*)d_in[1];
    float* out = (float*)d_out;

    int np = in_sizes[0] / 3;   // 1,993,728

    zero_counts_kernel<<<(CELLS + 255) / 256, 256>>>();
    idx_hist_kernel<<<(np + 255) / 256, 256>>>(geom, np);
    scan_block_kernel<<<SCAN_NB, 1024>>>();
    scan_spine_kernel<<<1, 128>>>();
    scan_add_kernel<<<SCAN_NB, 1024>>>();
    reorder_kernel<<<(np + 255) / 256, 256>>>(np);
    gather_kernel<<<CELLS / 32, 1024>>>(feats, out);
}